// round 13
// baseline (speedup 1.0000x reference)
#include <cuda_runtime.h>
#include <cuda_fp16.h>
#include <cstdint>

// Problem constants (fixed by the dataset)
#define NN 100000
#define NE 1600000
#define DD 64
#define CAP 64          // bucket capacity per node (Poisson(16): P(deg>64)~2e-22)

#define XS_STRIDE 72    // halves; 144B rows: 16B-aligned + conflict-free ldmatrix

// ---------------- device scratch (no allocations allowed) ----------------
// g_cnt relies on BSS zero-init; agg2 re-zeroes it (replay invariant).
__device__ __align__(256) int     g_cnt[NN];
__device__ __align__(256) int     g_bkt[(size_t)NN * CAP];   // bucket CSR
__device__ __align__(256) __half2 g_hn[(size_t)NN * 32];     // layer-1 msgs
__device__ __align__(256) __half2 g_hn2[(size_t)NN * 32];    // layer-2 msgs

// ------------- standalone bucket scatter: 4 edges/thread via int4 -----------
__global__ void k_scatter(const int* __restrict__ src,
                          const int* __restrict__ dst, int e4, int n) {
    int i = blockIdx.x * blockDim.x + threadIdx.x;
    if (i >= e4) return;
    int4 s4 = reinterpret_cast<const int4*>(src)[i];
    int4 d4 = reinterpret_cast<const int4*>(dst)[i];
    int dd[4] = {d4.x, d4.y, d4.z, d4.w};
    int ss[4] = {s4.x, s4.y, s4.z, s4.w};
#pragma unroll
    for (int q = 0; q < 4; q++) {
        if ((unsigned)dd[q] >= (unsigned)n || (unsigned)ss[q] >= (unsigned)n) continue;
        int slot = atomicAdd(&g_cnt[dd[q]], 1);
        if (slot < CAP) g_bkt[(size_t)dd[q] * CAP + slot] = ss[q];
    }
}

// ---------- shared device helpers (used by both GEMM-containing kernels) ----
__device__ __forceinline__ void stage_W(const float* __restrict__ W,
                                        __half* wt, int tid) {
    const float4* Wp4 = reinterpret_cast<const float4*>(W);
#pragma unroll
    for (int ii = 0; ii < 4; ii++) {
        int i4 = tid + 256 * ii;                 // 1024 float4 total
        float4 wv = Wp4[i4];
        int flat = i4 * 4;
        int k = flat >> 6;
        int nn = flat & 63;
        wt[(nn)     * XS_STRIDE + k] = __float2half_rn(wv.x);
        wt[(nn + 1) * XS_STRIDE + k] = __float2half_rn(wv.y);
        wt[(nn + 2) * XS_STRIDE + k] = __float2half_rn(wv.z);
        wt[(nn + 3) * XS_STRIDE + k] = __float2half_rn(wv.w);
    }
}

// MMA body: xs (A rows, fp16) x wt -> scaled fp16 back into xs -> out (global)
// Assumes xs/wt staged and __syncthreads() already done by caller.
__device__ __forceinline__ void mma_and_store(
    __half* xs, const __half* wt, __half2* gout, int base, int n, int tid) {
    int wid = tid >> 5, lane = tid & 31;
    int g = lane >> 2, t = lane & 3;
    uint32_t xs_u32 = (uint32_t)__cvta_generic_to_shared(xs);

    uint32_t afr[2][4][4];
#pragma unroll
    for (int mt = 0; mt < 2; mt++) {
        int rsh = wid * 32 + mt * 16 + (lane & 15);
#pragma unroll
        for (int kc = 0; kc < 4; kc++) {
            uint32_t addr = xs_u32 + rsh * (XS_STRIDE * 2) + kc * 32 + (lane >> 4) * 16;
            asm volatile("ldmatrix.sync.aligned.m8n8.x4.shared.b16 {%0,%1,%2,%3}, [%4];"
                         : "=r"(afr[mt][kc][0]), "=r"(afr[mt][kc][1]),
                           "=r"(afr[mt][kc][2]), "=r"(afr[mt][kc][3])
                         : "r"(addr));
        }
    }

    float c[8][2][4];
#pragma unroll
    for (int nt = 0; nt < 8; nt++)
#pragma unroll
        for (int mt = 0; mt < 2; mt++)
#pragma unroll
            for (int q = 0; q < 4; q++) c[nt][mt][q] = 0.f;

#pragma unroll
    for (int nt = 0; nt < 8; nt++) {
        uint32_t b0[4], b1[4];
        int nrow = nt * 8 + g;
#pragma unroll
        for (int kc = 0; kc < 4; kc++) {
            b0[kc] = *reinterpret_cast<const uint32_t*>(&wt[nrow * XS_STRIDE + kc * 16 + 2 * t]);
            b1[kc] = *reinterpret_cast<const uint32_t*>(&wt[nrow * XS_STRIDE + kc * 16 + 8 + 2 * t]);
        }
#pragma unroll
        for (int mt = 0; mt < 2; mt++) {
#pragma unroll
            for (int kc = 0; kc < 4; kc++) {
                asm volatile(
                    "mma.sync.aligned.m16n8k16.row.col.f32.f16.f16.f32 "
                    "{%0,%1,%2,%3}, {%4,%5,%6,%7}, {%8,%9}, {%0,%1,%2,%3};"
                    : "+f"(c[nt][mt][0]), "+f"(c[nt][mt][1]),
                      "+f"(c[nt][mt][2]), "+f"(c[nt][mt][3])
                    : "r"(afr[mt][kc][0]), "r"(afr[mt][kc][1]),
                      "r"(afr[mt][kc][2]), "r"(afr[mt][kc][3]),
                      "r"(b0[kc]), "r"(b1[kc]));
            }
        }
    }
    __syncthreads();   // all ldmatrix reads done; xs reusable

    // epilogue: scale by dinv(row) and park in shared (conflict-free)
#pragma unroll
    for (int mt = 0; mt < 2; mt++) {
        int rl = wid * 32 + mt * 16 + g;
        int r0 = base + rl, r1 = r0 + 8;
        float di0 = (r0 < n) ? rsqrtf((float)(g_cnt[r0] + 1)) : 0.f;
        float di1 = (r1 < n) ? rsqrtf((float)(g_cnt[r1] + 1)) : 0.f;
#pragma unroll
        for (int nt = 0; nt < 8; nt++) {
            int col = nt * 8 + 2 * t;
            *reinterpret_cast<__half2*>(&xs[rl * XS_STRIDE + col]) =
                __floats2half2_rn(c[nt][mt][0] * di0, c[nt][mt][1] * di0);
            *reinterpret_cast<__half2*>(&xs[(rl + 8) * XS_STRIDE + col]) =
                __floats2half2_rn(c[nt][mt][2] * di1, c[nt][mt][3] * di1);
        }
    }
    __syncthreads();

    // shared -> global, fully coalesced STG.128
    uint4* outp = reinterpret_cast<uint4*>(gout) + (size_t)base * 8;
    int limit = (min(256, n - base)) * 8;
#pragma unroll
    for (int ii = 0; ii < 8; ii++) {
        int i = tid + 256 * ii;
        if (i < limit) {
            int r = i >> 3, pc = i & 7;
            outp[i] = reinterpret_cast<uint4*>(&xs[r * XS_STRIDE])[pc];
        }
    }
}

// node-gather: returns relu(dinv*(hn[node]+sum hn[nbr]) + b) packed as uint4
__device__ __forceinline__ uint4 agg_node(const __half2* __restrict__ hn,
                                          const float* __restrict__ b,
                                          int node, int sub) {
    const uint4* hn4 = reinterpret_cast<const uint4*>(hn);
    int cnt = g_cnt[node];
    float di = rsqrtf((float)(cnt + 1));
    int len = min(cnt, CAP);
    const int4* bp = reinterpret_cast<const int4*>(g_bkt + (size_t)node * CAP);

    uint4 uself = hn4[(size_t)node * 8 + sub];
    float2 a0 = __half22float2(*reinterpret_cast<__half2*>(&uself.x));
    float2 a1 = __half22float2(*reinterpret_cast<__half2*>(&uself.y));
    float2 a2 = __half22float2(*reinterpret_cast<__half2*>(&uself.z));
    float2 a3 = __half22float2(*reinterpret_cast<__half2*>(&uself.w));
    float2 c0 = {0.f, 0.f}, c1 = {0.f, 0.f}, c2 = {0.f, 0.f}, c3 = {0.f, 0.f};

#define ACC_U4(U, X0, X1, X2, X3)                                         \
    {                                                                     \
        float2 f0 = __half22float2(*reinterpret_cast<__half2*>(&(U).x));  \
        float2 f1 = __half22float2(*reinterpret_cast<__half2*>(&(U).y));  \
        float2 f2 = __half22float2(*reinterpret_cast<__half2*>(&(U).z));  \
        float2 f3 = __half22float2(*reinterpret_cast<__half2*>(&(U).w));  \
        X0.x += f0.x; X0.y += f0.y; X1.x += f1.x; X1.y += f1.y;           \
        X2.x += f2.x; X2.y += f2.y; X3.x += f3.x; X3.y += f3.y;           \
    }
    int p = 0;
    for (; p + 4 <= len; p += 4) {
        int4 e = bp[p >> 2];
        uint4 u0 = hn4[(size_t)e.x * 8 + sub];
        uint4 u1 = hn4[(size_t)e.y * 8 + sub];
        uint4 u2 = hn4[(size_t)e.z * 8 + sub];
        uint4 u3 = hn4[(size_t)e.w * 8 + sub];
        ACC_U4(u0, a0, a1, a2, a3)
        ACC_U4(u1, c0, c1, c2, c3)
        ACC_U4(u2, a0, a1, a2, a3)
        ACC_U4(u3, c0, c1, c2, c3)
    }
    for (; p < len; p++) {
        int s = g_bkt[(size_t)node * CAP + p];
        uint4 u0 = hn4[(size_t)s * 8 + sub];
        ACC_U4(u0, a0, a1, a2, a3)
    }
#undef ACC_U4

    const float4* b4 = reinterpret_cast<const float4*>(b);
    float4 bA = b4[sub * 2], bB = b4[sub * 2 + 1];
    __half2 h0 = __floats2half2_rn(fmaxf((a0.x + c0.x) * di + bA.x, 0.f),
                                   fmaxf((a0.y + c0.y) * di + bA.y, 0.f));
    __half2 h1 = __floats2half2_rn(fmaxf((a1.x + c1.x) * di + bA.z, 0.f),
                                   fmaxf((a1.y + c1.y) * di + bA.w, 0.f));
    __half2 h2 = __floats2half2_rn(fmaxf((a2.x + c2.x) * di + bB.x, 0.f),
                                   fmaxf((a2.y + c2.y) * di + bB.y, 0.f));
    __half2 h3 = __floats2half2_rn(fmaxf((a3.x + c3.x) * di + bB.z, 0.f),
                                   fmaxf((a3.y + c3.y) * di + bB.w, 0.f));
    uint4 pk;
    pk.x = *reinterpret_cast<unsigned*>(&h0);
    pk.y = *reinterpret_cast<unsigned*>(&h1);
    pk.z = *reinterpret_cast<unsigned*>(&h2);
    pk.w = *reinterpret_cast<unsigned*>(&h3);
    return pk;
}

// -------- GEMM layer 1: g_hn[row] = fp16((emb@W1) * rsqrt(cnt+1)) ----------
__global__ void __launch_bounds__(256) k_gemm1(
    const float* __restrict__ emb, const float* __restrict__ W, int n) {
    __shared__ __half xs[256 * XS_STRIDE];
    __shared__ __half wt[64 * XS_STRIDE];
    int tid = threadIdx.x;
    int base = blockIdx.x * 256;

    {   // stage emb rows -> fp16 shared
        int row = base + tid;
        const float4* xr = reinterpret_cast<const float4*>(emb + (size_t)row * DD);
        bool v = row < n;
        __half2* dstp = reinterpret_cast<__half2*>(&xs[tid * XS_STRIDE]);
#pragma unroll
        for (int kk = 0; kk < 16; kk++) {
            float4 q = v ? xr[kk] : make_float4(0.f, 0.f, 0.f, 0.f);
            dstp[kk * 2]     = __floats2half2_rn(q.x, q.y);
            dstp[kk * 2 + 1] = __floats2half2_rn(q.z, q.w);
        }
    }
    stage_W(W, wt, tid);
    __syncthreads();
    mma_and_store(xs, wt, g_hn, base, n, tid);
}

// -------- FUSED agg(layer1) + GEMM layer 2 ----------------------------------
// Aggregates its 256 nodes from g_hn directly into shared (ReLU fp16 h1 tile),
// then runs the W2 MMA on it. h1 never touches global memory. Output -> g_hn2
// (separate buffer: other blocks still gather from g_hn).
__global__ void __launch_bounds__(256) k_agg_gemm(
    const float* __restrict__ b1, const float* __restrict__ W2, int n) {
    __shared__ __half xs[256 * XS_STRIDE];
    __shared__ __half wt[64 * XS_STRIDE];
    int tid = threadIdx.x;
    int base = blockIdx.x * 256;
    int sub = tid & 7;

    stage_W(W2, wt, tid);

    // agg 256 nodes in 8 passes of 32 nodes (8 lanes/node)
#pragma unroll 1
    for (int j = 0; j < 8; j++) {
        int rl = j * 32 + (tid >> 3);
        int node = base + rl;
        uint4 pk = make_uint4(0, 0, 0, 0);
        if (node < n) pk = agg_node(g_hn, b1, node, sub);
        *reinterpret_cast<uint4*>(&xs[rl * XS_STRIDE + sub * 8]) = pk;
    }
    __syncthreads();
    mma_and_store(xs, wt, g_hn2, base, n, tid);
}

// ---- agg layer 2: d_out = relu(dinv*(hn2[i]+sum hn2[s]) + b2); zero cnt ----
__global__ void __launch_bounds__(256) k_agg2(
    const float* __restrict__ b, float* __restrict__ dout, int n) {
    int tid = blockIdx.x * blockDim.x + threadIdx.x;
    int node = tid >> 3;
    int sub = tid & 7;
    if (node >= n) return;
    uint4 pk = agg_node(g_hn2, b, node, sub);        // fp16 relu'd result
    if (sub == 0) g_cnt[node] = 0;                   // clean for next replay
    // unpack to fp32 for output
    __half2 h0 = *reinterpret_cast<__half2*>(&pk.x);
    __half2 h1 = *reinterpret_cast<__half2*>(&pk.y);
    __half2 h2 = *reinterpret_cast<__half2*>(&pk.z);
    __half2 h3 = *reinterpret_cast<__half2*>(&pk.w);
    float2 f0 = __half22float2(h0), f1 = __half22float2(h1);
    float2 f2 = __half22float2(h2), f3 = __half22float2(h3);
    float4* op = reinterpret_cast<float4*>(dout + (size_t)node * DD + sub * 8);
    op[0] = make_float4(f0.x, f0.y, f1.x, f1.y);
    op[1] = make_float4(f2.x, f2.y, f3.x, f3.y);
}

// ---------------- launch (ONLY kernel launches — nothing else) ----------------
extern "C" void kernel_launch(void* const* d_in, const int* in_sizes, int n_in,
                              void* d_out, int out_size) {
    const float* emb = (const float*)d_in[0];
    const int*   ei  = (const int*)d_in[1];     // int32 (JAX x64 disabled)
    const float* W1  = (const float*)d_in[2];
    const float* b1  = (const float*)d_in[3];
    const float* W2  = (const float*)d_in[4];
    const float* b2  = (const float*)d_in[5];
    float*       out = (float*)d_out;

    int N = in_sizes[0] / DD;
    int E = in_sizes[1] / 2;
    const int* srcp = ei;       // edge_index[0]
    const int* dstp = ei + E;   // edge_index[1]
    int e4 = E / 4;
    int gblocks = (N + 255) / 256;

    k_scatter<<<(e4 + 255) / 256, 256>>>(srcp, dstp, e4, N);
    k_gemm1<<<gblocks, 256>>>(emb, W1, N);
    k_agg_gemm<<<gblocks, 256>>>(b1, W2, N);
    k_agg2<<<(N * 8 + 255) / 256, 256>>>(b2, out, N);   // launch #4 -> profiled
}

// round 14
// speedup vs baseline: 1.3837x; 1.3837x over previous
#include <cuda_runtime.h>
#include <cuda_fp16.h>
#include <cstdint>

// Problem constants (fixed by the dataset)
#define NN 100000
#define NE 1600000
#define DD 64
#define CAP 64          // bucket capacity per node (Poisson(16): P(deg>64)~2e-22)

#define XS_STRIDE 72    // halves; 144B rows: 16B-aligned + conflict-free ldmatrix

// ---------------- device scratch (no allocations allowed) ----------------
// g_cnt relies on BSS zero-init; agg layer-2 re-zeroes it (replay invariant).
__device__ __align__(256) int     g_cnt[NN];
__device__ __align__(256) int     g_bkt[(size_t)NN * CAP];   // bucket CSR
__device__ __align__(256) __half2 g_hn[(size_t)NN * 32];     // (x@W)*dinv, fp16
__device__ __align__(256) __half  g_h1h[(size_t)NN * DD];    // layer-1 out, fp16

// ------------- standalone bucket scatter: 4 edges/thread via int4 -----------
__global__ void k_scatter(const int* __restrict__ src,
                          const int* __restrict__ dst, int e4, int n) {
    int i = blockIdx.x * blockDim.x + threadIdx.x;
    if (i >= e4) return;
    int4 s4 = reinterpret_cast<const int4*>(src)[i];
    int4 d4 = reinterpret_cast<const int4*>(dst)[i];
    int dd[4] = {d4.x, d4.y, d4.z, d4.w};
    int ss[4] = {s4.x, s4.y, s4.z, s4.w};
#pragma unroll
    for (int q = 0; q < 4; q++) {
        if ((unsigned)dd[q] >= (unsigned)n || (unsigned)ss[q] >= (unsigned)n) continue;
        int slot = atomicAdd(&g_cnt[dd[q]], 1);
        if (slot < CAP) g_bkt[(size_t)dd[q] * CAP + slot] = ss[q];
    }
}

// -------- GEMM: g_hn[row] = fp16((x@W) * rsqrt(cnt[row]+1)) -----------------
// Block = 256 threads/8 warps/256 rows. mma.sync.m16n8k16 f32.f16.f16.f32.
// Epilogue: scale by dinv, frags -> shared -> coalesced STG.128.
__global__ void __launch_bounds__(256) k_gemm(
    const float* __restrict__ emb, const float* __restrict__ W,
    int layer, int n) {
    __shared__ __half xs[256 * XS_STRIDE];       // 36864 B
    __shared__ __half wt[64 * XS_STRIDE];        //  9216 B  (wt[n][k])
    int tid = threadIdx.x;
    int base = blockIdx.x * 256;

    // ---- stage x rows -> fp16 shared ----
    if (layer == 0) {
        int row = base + tid;
        const float4* xr = reinterpret_cast<const float4*>(emb + (size_t)row * DD);
        bool v = row < n;
        __half2* dstp = reinterpret_cast<__half2*>(&xs[tid * XS_STRIDE]);
#pragma unroll
        for (int kk = 0; kk < 16; kk++) {
            float4 q = v ? xr[kk] : make_float4(0.f, 0.f, 0.f, 0.f);
            dstp[kk * 2]     = __floats2half2_rn(q.x, q.y);
            dstp[kk * 2 + 1] = __floats2half2_rn(q.z, q.w);
        }
    } else {
        const uint4* inp = reinterpret_cast<const uint4*>(g_h1h);
        uint4 z = make_uint4(0, 0, 0, 0);
#pragma unroll
        for (int ii = 0; ii < 8; ii++) {
            int i = tid + 256 * ii;
            int r = i >> 3, pc = i & 7;
            int gr = base + r;
            uint4 v = (gr < n) ? inp[(size_t)gr * 8 + pc] : z;
            reinterpret_cast<uint4*>(&xs[r * XS_STRIDE])[pc] = v;
        }
    }
    // ---- stage W -> fp16 transposed shared (wt[n][k]) ----
    {
        const float4* Wp4 = reinterpret_cast<const float4*>(W);
#pragma unroll
        for (int ii = 0; ii < 4; ii++) {
            int i4 = tid + 256 * ii;             // 1024 float4 total
            float4 wv = Wp4[i4];
            int flat = i4 * 4;
            int k = flat >> 6;
            int nn = flat & 63;
            wt[(nn)     * XS_STRIDE + k] = __float2half_rn(wv.x);
            wt[(nn + 1) * XS_STRIDE + k] = __float2half_rn(wv.y);
            wt[(nn + 2) * XS_STRIDE + k] = __float2half_rn(wv.z);
            wt[(nn + 3) * XS_STRIDE + k] = __float2half_rn(wv.w);
        }
    }
    __syncthreads();

    int wid = tid >> 5, lane = tid & 31;
    int g = lane >> 2, t = lane & 3;
    uint32_t xs_u32 = (uint32_t)__cvta_generic_to_shared(xs);

    // A fragments via ldmatrix.x4
    uint32_t afr[2][4][4];
#pragma unroll
    for (int mt = 0; mt < 2; mt++) {
        int rsh = wid * 32 + mt * 16 + (lane & 15);
#pragma unroll
        for (int kc = 0; kc < 4; kc++) {
            uint32_t addr = xs_u32 + rsh * (XS_STRIDE * 2) + kc * 32 + (lane >> 4) * 16;
            asm volatile("ldmatrix.sync.aligned.m8n8.x4.shared.b16 {%0,%1,%2,%3}, [%4];"
                         : "=r"(afr[mt][kc][0]), "=r"(afr[mt][kc][1]),
                           "=r"(afr[mt][kc][2]), "=r"(afr[mt][kc][3])
                         : "r"(addr));
        }
    }

    float c[8][2][4];
#pragma unroll
    for (int nt = 0; nt < 8; nt++)
#pragma unroll
        for (int mt = 0; mt < 2; mt++)
#pragma unroll
            for (int q = 0; q < 4; q++) c[nt][mt][q] = 0.f;

#pragma unroll
    for (int nt = 0; nt < 8; nt++) {
        uint32_t b0[4], b1[4];
        int nrow = nt * 8 + g;
#pragma unroll
        for (int kc = 0; kc < 4; kc++) {
            b0[kc] = *reinterpret_cast<const uint32_t*>(&wt[nrow * XS_STRIDE + kc * 16 + 2 * t]);
            b1[kc] = *reinterpret_cast<const uint32_t*>(&wt[nrow * XS_STRIDE + kc * 16 + 8 + 2 * t]);
        }
#pragma unroll
        for (int mt = 0; mt < 2; mt++) {
#pragma unroll
            for (int kc = 0; kc < 4; kc++) {
                asm volatile(
                    "mma.sync.aligned.m16n8k16.row.col.f32.f16.f16.f32 "
                    "{%0,%1,%2,%3}, {%4,%5,%6,%7}, {%8,%9}, {%0,%1,%2,%3};"
                    : "+f"(c[nt][mt][0]), "+f"(c[nt][mt][1]),
                      "+f"(c[nt][mt][2]), "+f"(c[nt][mt][3])
                    : "r"(afr[mt][kc][0]), "r"(afr[mt][kc][1]),
                      "r"(afr[mt][kc][2]), "r"(afr[mt][kc][3]),
                      "r"(b0[kc]), "r"(b1[kc]));
            }
        }
    }
    __syncthreads();   // xs reuse

    // ---- epilogue: scale by dinv, frags -> shared (conflict-free) ----
#pragma unroll
    for (int mt = 0; mt < 2; mt++) {
        int rl = wid * 32 + mt * 16 + g;
        int r0 = base + rl, r1 = r0 + 8;
        float di0 = (r0 < n) ? rsqrtf((float)(g_cnt[r0] + 1)) : 0.f;
        float di1 = (r1 < n) ? rsqrtf((float)(g_cnt[r1] + 1)) : 0.f;
#pragma unroll
        for (int nt = 0; nt < 8; nt++) {
            int col = nt * 8 + 2 * t;
            *reinterpret_cast<__half2*>(&xs[rl * XS_STRIDE + col]) =
                __floats2half2_rn(c[nt][mt][0] * di0, c[nt][mt][1] * di0);
            *reinterpret_cast<__half2*>(&xs[(rl + 8) * XS_STRIDE + col]) =
                __floats2half2_rn(c[nt][mt][2] * di1, c[nt][mt][3] * di1);
        }
    }
    __syncthreads();

    // ---- shared -> global, fully coalesced STG.128 ----
    uint4* outp = reinterpret_cast<uint4*>(g_hn) + (size_t)base * 8;
    int limit = (min(256, n - base)) * 8;
#pragma unroll
    for (int ii = 0; ii < 8; ii++) {
        int i = tid + 256 * ii;
        if (i < limit) {
            int r = i >> 3, pc = i & 7;
            outp[i] = reinterpret_cast<uint4*>(&xs[r * XS_STRIDE])[pc];
        }
    }
}

// ---- aggregation: out = relu(dinv_d*(hn_d + sum_s hn_s) + b) ---------------
// 8 lanes/node (4 nodes/warp), uint4 row gathers. Inner loop sums 4 rows with
// a packed HADD2 tree (12 HADD2 / 4 edges) then drains once to fp32 — halves
// the cvt+add instruction stream vs fp32-per-edge (agg is issue-bound: R13
// ncu showed issue 50.6%, fma+alu 48%, L2 only 28%).
__global__ void __launch_bounds__(256) k_agg(
    const float* __restrict__ b, float* __restrict__ dout,
    int layer, int n) {
    int tid = blockIdx.x * blockDim.x + threadIdx.x;
    int node = tid >> 3;
    int sub = tid & 7;                 // owns half2[4*sub .. 4*sub+3]
    if (node >= n) return;
    const uint4* hn4 = reinterpret_cast<const uint4*>(g_hn);

    int cnt = g_cnt[node];
    float di = rsqrtf((float)(cnt + 1));
    int len = min(cnt, CAP);
    const int4* bp = reinterpret_cast<const int4*>(g_bkt) + (unsigned)(node * (CAP / 4));

    unsigned selfoff = (unsigned)(node * 8 + sub);
    uint4 uself = hn4[selfoff];
    float2 a0 = __half22float2(*reinterpret_cast<__half2*>(&uself.x));
    float2 a1 = __half22float2(*reinterpret_cast<__half2*>(&uself.y));
    float2 a2 = __half22float2(*reinterpret_cast<__half2*>(&uself.z));
    float2 a3 = __half22float2(*reinterpret_cast<__half2*>(&uself.w));

#define H2(v) (*reinterpret_cast<const __half2*>(&(v)))
    int p = 0;
    for (; p + 4 <= len; p += 4) {
        int4 e = bp[p >> 2];                      // broadcast across 8 lanes
        uint4 u0 = hn4[(unsigned)(e.x * 8 + sub)];
        uint4 u1 = hn4[(unsigned)(e.y * 8 + sub)];
        uint4 u2 = hn4[(unsigned)(e.z * 8 + sub)];
        uint4 u3 = hn4[(unsigned)(e.w * 8 + sub)];
        // fp16 pairwise tree per component, one fp32 drain per 4 edges
        __half2 t0 = __hadd2(__hadd2(H2(u0.x), H2(u1.x)), __hadd2(H2(u2.x), H2(u3.x)));
        __half2 t1 = __hadd2(__hadd2(H2(u0.y), H2(u1.y)), __hadd2(H2(u2.y), H2(u3.y)));
        __half2 t2 = __hadd2(__hadd2(H2(u0.z), H2(u1.z)), __hadd2(H2(u2.z), H2(u3.z)));
        __half2 t3 = __hadd2(__hadd2(H2(u0.w), H2(u1.w)), __hadd2(H2(u2.w), H2(u3.w)));
        float2 f0 = __half22float2(t0), f1 = __half22float2(t1);
        float2 f2 = __half22float2(t2), f3 = __half22float2(t3);
        a0.x += f0.x; a0.y += f0.y; a1.x += f1.x; a1.y += f1.y;
        a2.x += f2.x; a2.y += f2.y; a3.x += f3.x; a3.y += f3.y;
    }
    for (; p < len; p++) {
        int s = g_bkt[(unsigned)(node * CAP + p)];
        uint4 u0 = hn4[(unsigned)(s * 8 + sub)];
        float2 f0 = __half22float2(H2(u0.x)), f1 = __half22float2(H2(u0.y));
        float2 f2 = __half22float2(H2(u0.z)), f3 = __half22float2(H2(u0.w));
        a0.x += f0.x; a0.y += f0.y; a1.x += f1.x; a1.y += f1.y;
        a2.x += f2.x; a2.y += f2.y; a3.x += f3.x; a3.y += f3.y;
    }
#undef H2

    if (layer == 1 && sub == 0) g_cnt[node] = 0;   // clean for next replay

    const float4* b4 = reinterpret_cast<const float4*>(b);
    float4 bA = b4[sub * 2], bB = b4[sub * 2 + 1];
    float vA0 = fmaxf(a0.x * di + bA.x, 0.f);
    float vA1 = fmaxf(a0.y * di + bA.y, 0.f);
    float vA2 = fmaxf(a1.x * di + bA.z, 0.f);
    float vA3 = fmaxf(a1.y * di + bA.w, 0.f);
    float vB0 = fmaxf(a2.x * di + bB.x, 0.f);
    float vB1 = fmaxf(a2.y * di + bB.y, 0.f);
    float vB2 = fmaxf(a3.x * di + bB.z, 0.f);
    float vB3 = fmaxf(a3.y * di + bB.w, 0.f);

    if (layer == 0) {
        __half2 h0 = __floats2half2_rn(vA0, vA1);
        __half2 h1 = __floats2half2_rn(vA2, vA3);
        __half2 h2 = __floats2half2_rn(vB0, vB1);
        __half2 h3 = __floats2half2_rn(vB2, vB3);
        uint4 pk;
        pk.x = *reinterpret_cast<unsigned*>(&h0);
        pk.y = *reinterpret_cast<unsigned*>(&h1);
        pk.z = *reinterpret_cast<unsigned*>(&h2);
        pk.w = *reinterpret_cast<unsigned*>(&h3);
        reinterpret_cast<uint4*>(g_h1h + (size_t)node * DD)[sub] = pk;
    } else {
        float4* op = reinterpret_cast<float4*>(dout + (size_t)node * DD + sub * 8);
        op[0] = make_float4(vA0, vA1, vA2, vA3);
        op[1] = make_float4(vB0, vB1, vB2, vB3);
    }
}

// ---------------- launch (ONLY kernel launches — nothing else) ----------------
extern "C" void kernel_launch(void* const* d_in, const int* in_sizes, int n_in,
                              void* d_out, int out_size) {
    const float* emb = (const float*)d_in[0];
    const int*   ei  = (const int*)d_in[1];     // int32 (JAX x64 disabled)
    const float* W1  = (const float*)d_in[2];
    const float* b1  = (const float*)d_in[3];
    const float* W2  = (const float*)d_in[4];
    const float* b2  = (const float*)d_in[5];
    float*       out = (float*)d_out;

    int N = in_sizes[0] / DD;
    int E = in_sizes[1] / 2;
    const int* srcp = ei;       // edge_index[0]
    const int* dstp = ei + E;   // edge_index[1]
    int e4 = E / 4;             // int4 quads
    int gblocks = (N + 255) / 256;

    // preprocessing: single-pass bucket scatter (counts final before gemm1)
    k_scatter<<<(e4 + 255) / 256, 256>>>(srcp, dstp, e4, N);

    // layer 1
    k_gemm<<<gblocks, 256>>>(emb, W1, 0, N);
    k_agg<<<(N * 8 + 255) / 256, 256>>>(b1, out, 0, N);
    // layer 2  (launch #4 -> profiled: control, expect ~13.4us)
    k_gemm<<<gblocks, 256>>>(emb, W2, 1, N);
    k_agg<<<(N * 8 + 255) / 256, 256>>>(b2, out, 1, N);
}